// round 11
// baseline (speedup 1.0000x reference)
#include <cuda_runtime.h>
#include <math.h>
#include <stdint.h>

// NT-Xent loss. N=8192 rows (interleaved zjs/zis), D=256.
// score = 2*cos(i,j) in [-2,2] -> fixed-shift logsumexp:
//   loss_i = 2 + ln(sum_{j!=i} exp(2 d_ij - 2)) - 2 d_{i, i^1}
// Symmetric int8 IMMA GEMM. Persistent CTAs: 296 CTAs x ~7 tiles each,
// cross-tile 3-stage cp.async ring (pipeline unit = 32KB K-half), so next
// tile's loads hide under current tile's compute + epilogue.

#define NROWS 8192
#define DIM   256

__device__ __align__(16) int8_t g_q[NROWS * DIM];   // 2 MB quantized rows
__device__ __align__(16) float g_sc[NROWS];         // per-row dequant scale
__device__ float g_rowsum[NROWS];
__device__ float g_tdot[NROWS];

#define SMEM_TOTAL 98304   // 3 stages x 32 KB

// ---------------- helpers ----------------
__device__ __forceinline__ uint32_t smem_u32(const void* p) {
    uint32_t a;
    asm("{ .reg .u64 t; cvta.to.shared.u64 t, %1; cvt.u32.u64 %0, t; }"
        : "=r"(a) : "l"(p));
    return a;
}
__device__ __forceinline__ void cp16(uint32_t dst, const void* src) {
    asm volatile("cp.async.cg.shared.global [%0], [%1], 16;"
                 :: "r"(dst), "l"(src) : "memory");
}
__device__ __forceinline__ void ldsm_x4(uint32_t* r, uint32_t addr) {
    asm volatile("ldmatrix.sync.aligned.m8n8.x4.shared.b16 {%0,%1,%2,%3}, [%4];"
                 : "=r"(r[0]), "=r"(r[1]), "=r"(r[2]), "=r"(r[3]) : "r"(addr));
}
__device__ __forceinline__ void imma16832(int* c, const uint32_t* a,
                                          uint32_t b0, uint32_t b1) {
    asm volatile("mma.sync.aligned.m16n8k32.row.col.s32.s8.s8.s32 "
                 "{%0,%1,%2,%3}, {%4,%5,%6,%7}, {%8,%9}, {%0,%1,%2,%3};"
                 : "+r"(c[0]), "+r"(c[1]), "+r"(c[2]), "+r"(c[3])
                 : "r"(a[0]), "r"(a[1]), "r"(a[2]), "r"(a[3]), "r"(b0), "r"(b1));
}
__device__ __forceinline__ float fexp2(float x) {
    float e; asm("ex2.approx.ftz.f32 %0, %1;" : "=f"(e) : "f"(x)); return e;
}
__device__ __forceinline__ float flg2(float x) {
    float e; asm("lg2.approx.f32 %0, %1;" : "=f"(e) : "f"(x)); return e;
}

// ---------------------------------------------------------------------------
// Kernel 1: interleave + fp32 normalize + per-row int8 quantize.
// Also zeroes g_rowsum, g_tdot, and the output scalar.
// ---------------------------------------------------------------------------
__global__ void __launch_bounds__(256) normalize_kernel(
    const float* __restrict__ zis, const float* __restrict__ zjs,
    float* __restrict__ out) {
    int gtid = blockIdx.x * 256 + threadIdx.x;
    if (gtid < NROWS) { g_rowsum[gtid] = 0.f; g_tdot[gtid] = 0.f; }
    if (gtid == 0) out[0] = 0.f;

    int w = threadIdx.x >> 5, lid = threadIdx.x & 31;
    int row = blockIdx.x * 8 + w;
    const float* src = (row & 1) ? (zis + (size_t)(row >> 1) * DIM)
                                 : (zjs + (size_t)(row >> 1) * DIM);
    float4 v0 = *reinterpret_cast<const float4*>(src + lid * 4);
    float4 v1 = *reinterpret_cast<const float4*>(src + 128 + lid * 4);
    float s = v0.x*v0.x + v0.y*v0.y + v0.z*v0.z + v0.w*v0.w
            + v1.x*v1.x + v1.y*v1.y + v1.z*v1.z + v1.w*v1.w;
    float mx = fmaxf(fmaxf(fmaxf(fabsf(v0.x), fabsf(v0.y)),
                           fmaxf(fabsf(v0.z), fabsf(v0.w))),
                     fmaxf(fmaxf(fabsf(v1.x), fabsf(v1.y)),
                           fmaxf(fabsf(v1.z), fabsf(v1.w))));
    #pragma unroll
    for (int o = 16; o > 0; o >>= 1) {
        s  += __shfl_xor_sync(0xFFFFFFFF, s, o);
        mx  = fmaxf(mx, __shfl_xor_sync(0xFFFFFFFF, mx, o));
    }
    float inv = 1.0f / fmaxf(sqrtf(s), 1e-8f);
    float mxn = fmaxf(mx * inv, 1e-20f);
    if (lid == 0) g_sc[row] = mxn * (1.0f / 127.0f);

    float k = inv * (127.0f / mxn);
    int q0 = __float2int_rn(v0.x * k), q1 = __float2int_rn(v0.y * k);
    int q2 = __float2int_rn(v0.z * k), q3 = __float2int_rn(v0.w * k);
    int q4 = __float2int_rn(v1.x * k), q5 = __float2int_rn(v1.y * k);
    int q6 = __float2int_rn(v1.z * k), q7 = __float2int_rn(v1.w * k);
    uint32_t w0 = (q0 & 0xff) | ((q1 & 0xff) << 8)
                | ((q2 & 0xff) << 16) | ((q3 & 0xff) << 24);
    uint32_t w1 = (q4 & 0xff) | ((q5 & 0xff) << 8)
                | ((q6 & 0xff) << 16) | ((q7 & 0xff) << 24);
    uint32_t* dst = reinterpret_cast<uint32_t*>(g_q + (size_t)row * DIM);
    dst[lid]      = w0;
    dst[32 + lid] = w1;
}

// ---------------------------------------------------------------------------
// Kernel 2: persistent IMMA GEMM over the 2080-tile upper triangle.
// 296 CTAs; CTA p handles 7 (+1 if p<8) consecutive tiles. Pipeline unit =
// one K-half (A-half 16KB + B-half 16KB) in a 3-stage smem ring.
// 8 warps (2m x 4n), warp tile 64x32.
// ---------------------------------------------------------------------------
__global__ void __launch_bounds__(256, 2) gemm_kernel() {
    const int p = blockIdx.x;
    const int cnt   = 7 + (p < 8 ? 1 : 0);
    const int tbase = p * 7 + (p < 8 ? p : 8);
    const int H = 2 * cnt;                     // halves to process

    extern __shared__ __align__(16) char smem[];
    const uint32_t sb = smem_u32(smem);
    const int tid = threadIdx.x;
    const int lid = tid & 31;
    const int wid = tid >> 5;
    const int wm = wid >> 2;
    const int wn = wid & 3;
    const int wrow = wm * 64;
    const int wcol = wn * 32;

    // decode flat tile index -> (band by, col bx)
    auto decode = [&](int t, int& by, int& bx) {
        int yy = t / 65, xx = t - yy * 65;
        if (xx < 64 - yy) { by = yy;      bx = yy + xx; }
        else              { by = 63 - yy; bx = xx - 1;  }
    };

    // issue one K-half of tile (by,bx) into stage s; diag loads A only.
    auto issue_half = [&](int by, int bx, bool diag, int k, int s) {
        uint32_t dA = sb + (uint32_t)s * 32768u;
        const char* srcA = (const char*)g_q + (size_t)by * 32768 + k * 128;
        #pragma unroll
        for (int it = 0; it < 4; it++) {
            int i = it * 256 + tid;
            int r = i >> 3, g = i & 7;
            uint32_t off = (uint32_t)(r * 128 + ((g * 16) ^ ((r & 7) << 4)));
            cp16(dA + off, srcA + (size_t)r * 256 + g * 16);
        }
        if (!diag) {
            uint32_t dB = dA + 16384u;
            const char* srcB = (const char*)g_q + (size_t)bx * 32768 + k * 128;
            #pragma unroll
            for (int it = 0; it < 4; it++) {
                int i = it * 256 + tid;
                int r = i >> 3, g = i & 7;
                uint32_t off = (uint32_t)(r * 128 + ((g * 16) ^ ((r & 7) << 4)));
                cp16(dB + off, srcB + (size_t)r * 256 + g * 16);
            }
        }
        asm volatile("cp.async.commit_group;" ::: "memory");
    };

    const int lg = lid & 7;
    const int ltile = lid >> 3;
    const int trow8 = (ltile & 1) * 8;
    const int tk16 = (ltile >> 1) * 16;

    int c[4][4][4];
    #pragma unroll
    for (int mi = 0; mi < 4; mi++)
        #pragma unroll
        for (int ni = 0; ni < 4; ni++)
            #pragma unroll
            for (int q = 0; q < 4; q++) c[mi][ni][q] = 0;

    auto compute = [&](int s, bool diag) {
        uint32_t asb = sb + (uint32_t)s * 32768u;
        uint32_t bsb = diag ? asb : (asb + 16384u);
        #pragma unroll
        for (int k32 = 0; k32 < 4; k32++) {
            int kb = k32 * 32 + tk16;
            uint32_t a[4][4], bb[2][4];
            #pragma unroll
            for (int mi = 0; mi < 4; mi++) {
                int m = wrow + mi * 16 + trow8 + lg;
                ldsm_x4(a[mi], asb + (uint32_t)(m * 128 + (kb ^ ((m & 7) << 4))));
            }
            #pragma unroll
            for (int nb = 0; nb < 2; nb++) {
                int n = wcol + nb * 16 + trow8 + lg;
                ldsm_x4(bb[nb], bsb + (uint32_t)(n * 128 + (kb ^ ((n & 7) << 4))));
            }
            #pragma unroll
            for (int mi = 0; mi < 4; mi++) {
                #pragma unroll
                for (int ni = 0; ni < 4; ni++) {
                    const uint32_t* B = bb[ni >> 1];
                    uint32_t b0 = (ni & 1) ? B[1] : B[0];
                    uint32_t b1 = (ni & 1) ? B[3] : B[2];
                    imma16832(c[mi][ni], a[mi], b0, b1);
                }
            }
        }
    };

    const float C1 = 2.885390081777927f;        // 2*log2(e)
    const float IC1 = 0.34657359027997264f;     // ln2/2

    auto epilogue = [&](int by, int bx, bool diag) {
        const int row0 = by * 128, col0 = bx * 128;
        // scales straight from global (L1-resident 32 KB array)
        float s0c[4], s1c[4];
        #pragma unroll
        for (int mi = 0; mi < 4; mi++) {
            int rl0 = wrow + mi * 16 + (lid >> 2);
            s0c[mi] = g_sc[row0 + rl0] * C1;
            s1c[mi] = g_sc[row0 + rl0 + 8] * C1;
        }
        float2 cscr[4];
        #pragma unroll
        for (int ni = 0; ni < 4; ni++)
            cscr[ni] = ((const float2*)g_sc)[bx * 64 + wn * 16 + ni * 4 + (lid & 3)];

        float rs[4][2], cs[4][2];
        #pragma unroll
        for (int i = 0; i < 4; i++) { rs[i][0]=rs[i][1]=0.f; cs[i][0]=cs[i][1]=0.f; }

        #pragma unroll
        for (int mi = 0; mi < 4; mi++) {
            int r0 = row0 + wrow + mi * 16 + (lid >> 2);
            int r1 = r0 + 8;
            #pragma unroll
            for (int ni = 0; ni < 4; ni++) {
                int cb = col0 + wcol + ni * 8 + (lid & 3) * 2;
                float sc0 = cscr[ni].x, sc1 = cscr[ni].y;
                float d0 = (float)c[mi][ni][0] * (s0c[mi] * sc0);
                float d1 = (float)c[mi][ni][1] * (s0c[mi] * sc1);
                float d2 = (float)c[mi][ni][2] * (s1c[mi] * sc0);
                float d3 = (float)c[mi][ni][3] * (s1c[mi] * sc1);
                float e0 = fexp2(d0 - C1);
                float e1 = fexp2(d1 - C1);
                float e2 = fexp2(d2 - C1);
                float e3 = fexp2(d3 - C1);
                if (diag) {
                    if (cb     == r0) e0 = 0.f;
                    if (cb + 1 == r0) e1 = 0.f;
                    if (cb     == r1) e2 = 0.f;
                    if (cb + 1 == r1) e3 = 0.f;
                    if (cb     == (r0 ^ 1)) g_tdot[r0] = d0 * IC1;
                    if (cb + 1 == (r0 ^ 1)) g_tdot[r0] = d1 * IC1;
                    if (cb     == (r1 ^ 1)) g_tdot[r1] = d2 * IC1;
                    if (cb + 1 == (r1 ^ 1)) g_tdot[r1] = d3 * IC1;
                }
                rs[mi][0] += e0 + e1;
                rs[mi][1] += e2 + e3;
                cs[ni][0] += e0 + e2;
                cs[ni][1] += e1 + e3;
            }
        }
        #pragma unroll
        for (int mi = 0; mi < 4; mi++) {
            #pragma unroll
            for (int h = 0; h < 2; h++) {
                float v = rs[mi][h];
                v += __shfl_xor_sync(0xFFFFFFFF, v, 1);
                v += __shfl_xor_sync(0xFFFFFFFF, v, 2);
                if ((lid & 3) == 0)
                    atomicAdd(&g_rowsum[row0 + wrow + mi*16 + (lid >> 2) + h*8], v);
            }
        }
        if (!diag) {
            #pragma unroll
            for (int ni = 0; ni < 4; ni++) {
                #pragma unroll
                for (int h = 0; h < 2; h++) {
                    float v = cs[ni][h];
                    v += __shfl_xor_sync(0xFFFFFFFF, v, 4);
                    v += __shfl_xor_sync(0xFFFFFFFF, v, 8);
                    v += __shfl_xor_sync(0xFFFFFFFF, v, 16);
                    if (lid < 4)
                        atomicAdd(&g_rowsum[col0 + wcol + ni*8 + lid*2 + h], v);
                }
            }
        }
        // reset accumulators for next tile
        #pragma unroll
        for (int mi = 0; mi < 4; mi++)
            #pragma unroll
            for (int ni = 0; ni < 4; ni++)
                #pragma unroll
                for (int q = 0; q < 4; q++) c[mi][ni][q] = 0;
    };

    // ---- prologue: issue halves 0 and 1 ----
    {
        int by, bx;
        decode(tbase, by, bx);
        bool dg = (bx == by);
        issue_half(by, bx, dg, 0, 0);
        issue_half(by, bx, dg, 1, 1);
    }

    // ---- main pipeline over halves ----
    for (int h = 0; h < H; h++) {
        const int s = h % 3;
        if (h == H - 1)
            asm volatile("cp.async.wait_group 0;" ::: "memory");
        else
            asm volatile("cp.async.wait_group 1;" ::: "memory");
        __syncthreads();    // all threads' half-h data visible; stage (h+2)%3
                            // was consumed in compute(h-1) by all warps

        if (h + 2 < H) {
            int t2 = tbase + ((h + 2) >> 1);
            int by2, bx2;
            decode(t2, by2, bx2);
            issue_half(by2, bx2, bx2 == by2, (h + 2) & 1, (h + 2) % 3);
        }

        int t = tbase + (h >> 1);
        int by, bx;
        decode(t, by, bx);
        bool dg = (bx == by);
        compute(s, dg);
        if (h & 1) epilogue(by, bx, dg);
    }
}

// ---------------------------------------------------------------------------
// Kernel 3: final reduction -> mean loss (32 blocks, atomic combine).
// ---------------------------------------------------------------------------
__global__ void __launch_bounds__(256) finalize_kernel(float* __restrict__ out) {
    int r = blockIdx.x * 256 + threadIdx.x;
    const float LN2 = 0.6931471805599453f;
    float acc = 2.f + LN2 * flg2(g_rowsum[r]) - 2.f * g_tdot[r];
    #pragma unroll
    for (int o = 16; o > 0; o >>= 1) acc += __shfl_xor_sync(0xFFFFFFFF, acc, o);
    __shared__ float sh[8];
    int w = threadIdx.x >> 5, l = threadIdx.x & 31;
    if (l == 0) sh[w] = acc;
    __syncthreads();
    if (threadIdx.x < 8) {
        float v = sh[threadIdx.x];
        v += __shfl_xor_sync(0xFF, v, 1);
        v += __shfl_xor_sync(0xFF, v, 2);
        v += __shfl_xor_sync(0xFF, v, 4);
        if (threadIdx.x == 0) atomicAdd(out, v * (1.0f / (float)NROWS));
    }
}

// ---------------------------------------------------------------------------
extern "C" void kernel_launch(void* const* d_in, const int* in_sizes, int n_in,
                              void* d_out, int out_size) {
    const float* zis = (const float*)d_in[0];
    const float* zjs = (const float*)d_in[1];
    float* out = (float*)d_out;

    cudaFuncSetAttribute(gemm_kernel,
                         cudaFuncAttributeMaxDynamicSharedMemorySize, SMEM_TOTAL);

    normalize_kernel<<<NROWS / 8, 256>>>(zis, zjs, out);
    gemm_kernel<<<296, 256, SMEM_TOTAL>>>();
    finalize_kernel<<<NROWS / 256, 256>>>(out);
}